// round 10
// baseline (speedup 1.0000x reference)
#include <cuda_runtime.h>
#include <cuda_fp16.h>
#include <cuda_bf16.h>
#include <math.h>
#include <stdint.h>

#define NN 4096
#define DD 512
#define INV_EPS 0.125f
#define STABZ 1e-8f

// ---- device scratch (no allocations allowed) ----
__device__ __nv_bfloat16 g_Sh[(size_t)NN * DD];
__device__ __nv_bfloat16 g_Sl[(size_t)NN * DD];
__device__ __nv_bfloat16 g_Th[(size_t)NN * DD];
__device__ __nv_bfloat16 g_Tl[(size_t)NN * DD];
__device__ float  g_u[NN];
__device__ float  g_v[NN];
__device__ float  g_sn[NN];
__device__ float  g_tn[NN];
__device__ __half g_Kh[(size_t)NN * NN];     // 32 MB fp16 Gibbs kernel for Sinkhorn matvecs
__device__ float  g_colpart[128 * NN];
__device__ float  g_losspart[NN];

// ================= helpers =================
__device__ __forceinline__ uint32_t s2u(const void* p) {
    uint32_t a;
    asm("{ .reg .u64 t; cvta.to.shared.u64 t, %1; cvt.u32.u64 %0, t; }" : "=r"(a) : "l"(p));
    return a;
}
#define SW128(o) ((o) ^ (((o) >> 3) & 0x70))

__device__ __forceinline__ void cp16(uint32_t dst, const void* src) {
    asm volatile("cp.async.cg.shared.global [%0], [%1], 16;" :: "r"(dst), "l"(src));
}

__device__ __forceinline__ void ldm4(uint32_t& r0, uint32_t& r1, uint32_t& r2, uint32_t& r3,
                                     uint32_t addr) {
    asm volatile("ldmatrix.sync.aligned.m8n8.x4.shared.b16 {%0,%1,%2,%3}, [%4];"
                 : "=r"(r0), "=r"(r1), "=r"(r2), "=r"(r3) : "r"(addr));
}

__device__ __forceinline__ void mma16816(float* c, const uint32_t* a, const uint32_t* b) {
    asm volatile(
        "mma.sync.aligned.m16n8k16.row.col.f32.bf16.bf16.f32 "
        "{%0,%1,%2,%3}, {%4,%5,%6,%7}, {%8,%9}, {%0,%1,%2,%3};"
        : "+f"(c[0]), "+f"(c[1]), "+f"(c[2]), "+f"(c[3])
        : "r"(a[0]), "r"(a[1]), "r"(a[2]), "r"(a[3]), "r"(b[0]), "r"(b[1]));
}

// ================= fused norm + split kernel =================
// one pass over S (y=0) / T (y=1): squared row norms + bf16 hi/lo split
__global__ void cvt_norm_kernel(const float* __restrict__ S, const float* __restrict__ T) {
    const float* src = blockIdx.y ? T : S;
    __nv_bfloat16* hi = blockIdx.y ? g_Th : g_Sh;
    __nv_bfloat16* lo = blockIdx.y ? g_Tl : g_Sl;
    float*        dst = blockIdx.y ? g_tn : g_sn;
    const int row = blockIdx.x;
    const int base = row * DD + threadIdx.x * 4;
    float4 x = *(const float4*)(src + base);

    __nv_bfloat16 h0 = __float2bfloat16_rn(x.x);
    __nv_bfloat16 h1 = __float2bfloat16_rn(x.y);
    __nv_bfloat16 h2 = __float2bfloat16_rn(x.z);
    __nv_bfloat16 h3 = __float2bfloat16_rn(x.w);
    __nv_bfloat16 l0 = __float2bfloat16_rn(x.x - __bfloat162float(h0));
    __nv_bfloat16 l1 = __float2bfloat16_rn(x.y - __bfloat162float(h1));
    __nv_bfloat16 l2 = __float2bfloat16_rn(x.z - __bfloat162float(h2));
    __nv_bfloat16 l3 = __float2bfloat16_rn(x.w - __bfloat162float(h3));
    *(__nv_bfloat162*)(hi + base)     = __halves2bfloat162(h0, h1);
    *(__nv_bfloat162*)(hi + base + 2) = __halves2bfloat162(h2, h3);
    *(__nv_bfloat162*)(lo + base)     = __halves2bfloat162(l0, l1);
    *(__nv_bfloat162*)(lo + base + 2) = __halves2bfloat162(l2, l3);

    float s = x.x * x.x + x.y * x.y + x.z * x.z + x.w * x.w;
    #pragma unroll
    for (int o = 16; o > 0; o >>= 1) s += __shfl_down_sync(0xffffffffu, s, o);
    __shared__ float sh[4];
    if ((threadIdx.x & 31) == 0) sh[threadIdx.x >> 5] = s;
    __syncthreads();
    if (threadIdx.x == 0) dst[row] = sh[0] + sh[1] + sh[2] + sh[3];
}

__global__ void init_v_kernel() {
    int i = blockIdx.x * 256 + threadIdx.x;
    if (i < NN) g_v[i] = 1.0f;
}

// ================= mma.sync GEMM + fused epilogue =================
// D = S@T^T via 3 bf16 products (hh + lh + hl) -> ~fp32 precision.
// 128x128 CTA tile, BK=64, 3-stage cp.async pipeline, ONE barrier per chunk.
#define TILE_B 16384                  // one 128x64 bf16 tile
#define STAGE_B (4 * TILE_B)          // Ah, Bh, Al, Bl = 64 KB
#define SMEM_DYN (3 * STAGE_B)        // 196608 (3 stages)

__global__ __launch_bounds__(512, 1)
void gemm_kernel(float* __restrict__ Cout) {
    extern __shared__ char smem[];
    const uint32_t sb = s2u(smem);
    const int tid = threadIdx.x, wid = tid >> 5, lid = tid & 31;
    const int wr = wid & 3, wc = wid >> 2;       // warp tile: rows wr*32, cols wc*32
    const int row0 = blockIdx.y * 128;
    const int col0 = blockIdx.x * 128;

    const __nv_bfloat16* gA[4];
    gA[0] = g_Sh + (size_t)row0 * DD;
    gA[1] = g_Th + (size_t)col0 * DD;
    gA[2] = g_Sl + (size_t)row0 * DD;
    gA[3] = g_Tl + (size_t)col0 * DD;

    // per-thread load coords: each tile = 1024 chunks of 16B; 512 threads -> 2 per tile
    const int lrow0 = tid >> 3, lrow1 = (tid + 512) >> 3;
    const int lcb = tid & 7;

    // ldmatrix per-lane address components (validated mapping)
    const int mi = lid >> 3, r8 = lid & 7;
    const int a_row = wr * 32 + (mi & 1) * 8 + r8;        // + m*16
    const int a_cb  = (mi >> 1) * 16;                     // + ks*32
    const int b_row = wc * 32 + (mi & 2) * 4 + r8;        // + g*16
    const int b_cb  = (mi & 1) * 16;                      // + ks*32

    float acc[2][4][4];
    #pragma unroll
    for (int m = 0; m < 2; m++)
        #pragma unroll
        for (int n = 0; n < 4; n++)
            #pragma unroll
            for (int q = 0; q < 4; q++) acc[m][n][q] = 0.0f;

    // prologue: load chunks 0,1 into stages 0,1
    #pragma unroll
    for (int s = 0; s < 2; s++) {
        #pragma unroll
        for (int t4 = 0; t4 < 4; t4++) {
            uint32_t tb = sb + s * STAGE_B + t4 * TILE_B;
            const __nv_bfloat16* g = gA[t4] + s * 64;
            cp16(tb + SW128((uint32_t)(lrow0 * 128 + lcb * 16)),
                 (const void*)(g + (size_t)lrow0 * DD + lcb * 8));
            cp16(tb + SW128((uint32_t)(lrow1 * 128 + lcb * 16)),
                 (const void*)(g + (size_t)lrow1 * DD + lcb * 8));
        }
        asm volatile("cp.async.commit_group;");
    }

    for (int ch = 0; ch < 8; ch++) {
        // stage ch ready when <= (newest_committed - ch) groups outstanding
        if (ch < 7) asm volatile("cp.async.wait_group 1;" ::: "memory");
        else        asm volatile("cp.async.wait_group 0;" ::: "memory");
        // single barrier: data-ready for everyone AND stage (ch-1) fully consumed
        __syncthreads();

        if (ch < 6) {
            const uint32_t nxt = sb + ((ch + 2) % 3) * STAGE_B;
            #pragma unroll
            for (int t4 = 0; t4 < 4; t4++) {
                uint32_t tb = nxt + t4 * TILE_B;
                const __nv_bfloat16* g = gA[t4] + (ch + 2) * 64;
                cp16(tb + SW128((uint32_t)(lrow0 * 128 + lcb * 16)),
                     (const void*)(g + (size_t)lrow0 * DD + lcb * 8));
                cp16(tb + SW128((uint32_t)(lrow1 * 128 + lcb * 16)),
                     (const void*)(g + (size_t)lrow1 * DD + lcb * 8));
            }
            asm volatile("cp.async.commit_group;");
        }

        const uint32_t cur = sb + (ch % 3) * STAGE_B;
        const uint32_t tAh = cur, tBh = cur + TILE_B, tAl = cur + 2 * TILE_B, tBl = cur + 3 * TILE_B;
        #pragma unroll
        for (int ks = 0; ks < 4; ks++) {
            const int cb = ks * 32;
            uint32_t ah[2][4], al[2][4], bh[4][2], bl[4][2];
            #pragma unroll
            for (int m = 0; m < 2; m++) {
                uint32_t off = SW128((uint32_t)((a_row + m * 16) * 128 + a_cb + cb));
                ldm4(ah[m][0], ah[m][1], ah[m][2], ah[m][3], tAh + off);
                ldm4(al[m][0], al[m][1], al[m][2], al[m][3], tAl + off);
            }
            #pragma unroll
            for (int g = 0; g < 2; g++) {
                uint32_t off = SW128((uint32_t)((b_row + g * 16) * 128 + b_cb + cb));
                ldm4(bh[2 * g][0], bh[2 * g][1], bh[2 * g + 1][0], bh[2 * g + 1][1], tBh + off);
                ldm4(bl[2 * g][0], bl[2 * g][1], bl[2 * g + 1][0], bl[2 * g + 1][1], tBl + off);
            }
            #pragma unroll
            for (int m = 0; m < 2; m++)
                #pragma unroll
                for (int n = 0; n < 4; n++) {
                    mma16816(acc[m][n], ah[m], bh[n]);
                    mma16816(acc[m][n], al[m], bh[n]);
                    mma16816(acc[m][n], ah[m], bl[n]);
                }
        }
    }
    __syncthreads();   // epilogue smem region overlaps stages still being read

    // ---- epilogue: convert to C, stage in smem, coalesced global stores ----
    float* sm = (float*)smem;    // 128 x 129 fp32
    const int qr = lid >> 2, qc = lid & 3;
    #pragma unroll
    for (int m = 0; m < 2; m++) {
        const int rb = wr * 32 + m * 16 + qr;
        const float sn0 = g_sn[row0 + rb];
        const float sn1 = g_sn[row0 + rb + 8];
        #pragma unroll
        for (int n = 0; n < 4; n++) {
            const int cl = wc * 32 + n * 8 + 2 * qc;
            const float tn0 = __ldg(&g_tn[col0 + cl]);
            const float tn1 = __ldg(&g_tn[col0 + cl + 1]);
            sm[rb * 129 + cl]           = sqrtf(fmaxf(sn0 + tn0 - 2.0f * acc[m][n][0], 0.0f));
            sm[rb * 129 + cl + 1]       = sqrtf(fmaxf(sn0 + tn1 - 2.0f * acc[m][n][1], 0.0f));
            sm[(rb + 8) * 129 + cl]     = sqrtf(fmaxf(sn1 + tn0 - 2.0f * acc[m][n][2], 0.0f));
            sm[(rb + 8) * 129 + cl + 1] = sqrtf(fmaxf(sn1 + tn1 - 2.0f * acc[m][n][3], 0.0f));
        }
    }
    __syncthreads();

    #pragma unroll 4
    for (int it = 0; it < 32; it++) {
        int lin = it * 512 + tid;
        int r = lin >> 7, c = lin & 127;
        Cout[(size_t)(row0 + r) * NN + col0 + c] = sm[r * 129 + c];
    }
    __half2* Kh2 = (__half2*)g_Kh;
    #pragma unroll 4
    for (int it = 0; it < 16; it++) {
        int lin = it * 512 + tid;
        int r = lin >> 6, c2 = lin & 63;
        float a = sm[r * 129 + 2 * c2];
        float b = sm[r * 129 + 2 * c2 + 1];
        Kh2[((size_t)(row0 + r) * NN + col0) / 2 + c2] =
            __floats2half2_rn(__expf(-a * INV_EPS), __expf(-b * INV_EPS));
    }
}

// ================= Sinkhorn =================
// 512 threads, one uint4 per thread -> all loads in flight at once
__global__ __launch_bounds__(512)
void row_mv_kernel() {
    const int i = blockIdx.x;
    const uint4*  Kr = (const uint4*)(g_Kh + (size_t)i * NN);   // 512 uint4 per row
    const float4* V4 = (const float4*)g_v;
    const int tid = threadIdx.x;
    uint4 q = Kr[tid];
    float4 v0 = V4[2 * tid], v1 = V4[2 * tid + 1];
    float2 f0 = __half22float2(*(const __half2*)&q.x);
    float2 f1 = __half22float2(*(const __half2*)&q.y);
    float2 f2 = __half22float2(*(const __half2*)&q.z);
    float2 f3 = __half22float2(*(const __half2*)&q.w);
    float sum = f0.x * v0.x;
    sum = fmaf(f0.y, v0.y, sum);
    sum = fmaf(f1.x, v0.z, sum); sum = fmaf(f1.y, v0.w, sum);
    sum = fmaf(f2.x, v1.x, sum); sum = fmaf(f2.y, v1.y, sum);
    sum = fmaf(f3.x, v1.z, sum); sum = fmaf(f3.y, v1.w, sum);
    #pragma unroll
    for (int o = 16; o > 0; o >>= 1) sum += __shfl_down_sync(0xffffffffu, sum, o);
    __shared__ float sh[16];
    if ((tid & 31) == 0) sh[tid >> 5] = sum;
    __syncthreads();
    if (tid == 0) {
        float t = 0.0f;
        #pragma unroll
        for (int w = 0; w < 16; w++) t += sh[w];
        g_u[i] = (1.0f / NN) / (t + STABZ);
    }
}

// partials over 32-row chunks: grid (2, 128) = 256 blocks
__global__ __launch_bounds__(256)
void col_mv_part_kernel() {
    const int cb = blockIdx.x * 256 + threadIdx.x;   // uint4 index within row (0..511)
    const int i0 = blockIdx.y * 32;
    __shared__ float ush[32];
    if (threadIdx.x < 32) ush[threadIdx.x] = g_u[i0 + threadIdx.x];
    __syncthreads();
    float a0 = 0, a1 = 0, a2 = 0, a3 = 0, a4 = 0, a5 = 0, a6 = 0, a7 = 0;
    #pragma unroll 8
    for (int ii = 0; ii < 32; ii++) {
        uint4 q = *(const uint4*)(g_Kh + (size_t)(i0 + ii) * NN + cb * 8);
        float u = ush[ii];
        float2 f0 = __half22float2(*(const __half2*)&q.x);
        float2 f1 = __half22float2(*(const __half2*)&q.y);
        float2 f2 = __half22float2(*(const __half2*)&q.z);
        float2 f3 = __half22float2(*(const __half2*)&q.w);
        a0 = fmaf(f0.x, u, a0); a1 = fmaf(f0.y, u, a1);
        a2 = fmaf(f1.x, u, a2); a3 = fmaf(f1.y, u, a3);
        a4 = fmaf(f2.x, u, a4); a5 = fmaf(f2.y, u, a5);
        a6 = fmaf(f3.x, u, a6); a7 = fmaf(f3.y, u, a7);
    }
    float4* P = (float4*)(g_colpart + blockIdx.y * NN + cb * 8);
    P[0] = make_float4(a0, a1, a2, a3);
    P[1] = make_float4(a4, a5, a6, a7);
}

__global__ void col_reduce_kernel() {
    int j = blockIdx.x * 256 + threadIdx.x;
    float s = 0.0f;
    #pragma unroll 8
    for (int ch = 0; ch < 128; ch++) s += g_colpart[ch * NN + j];
    g_v[j] = (1.0f / NN) / (s + STABZ);
}

// ================= final: coupling = u*exp(-C/8)*v, loss partials =================
// coup/Cc row bases are  (1 mod 4) floats off 16B alignment: body uses float4
// from element 3 (aligned), head elems 0..2 and tail elem 4095 handled scalar.
__global__ __launch_bounds__(256)
void final_kernel(float* __restrict__ coup, const float* __restrict__ Cc) {
    __shared__ float vs[NN];
    const int tid = threadIdx.x;
    {
        const float4* V4 = (const float4*)g_v;
        float4* S4 = (float4*)vs;
        #pragma unroll
        for (int p = 0; p < 4; p++) S4[tid + p * 256] = V4[tid + p * 256];
    }
    __syncthreads();

    const int i = blockIdx.x;
    const float ui = g_u[i];
    const float* Cr = Cc + (size_t)i * NN;
    float*       Or = coup + (size_t)i * NN;
    const float4* Cr4 = (const float4*)(Cr + 3);   // 16B aligned
    float4*       Or4 = (float4*)(Or + 3);
    float lp = 0.0f;

    #pragma unroll
    for (int p = 0; p < 4; p++) {
        int idx = tid + p * 256;
        if (idx < 1023) {
            float4 c = Cr4[idx];
            int j = 3 + 4 * idx;
            float4 o;
            o.x = ui * __expf(-c.x * INV_EPS) * vs[j];
            o.y = ui * __expf(-c.y * INV_EPS) * vs[j + 1];
            o.z = ui * __expf(-c.z * INV_EPS) * vs[j + 2];
            o.w = ui * __expf(-c.w * INV_EPS) * vs[j + 3];
            Or4[idx] = o;
            lp = fmaf(o.x, c.x, lp); lp = fmaf(o.y, c.y, lp);
            lp = fmaf(o.z, c.z, lp); lp = fmaf(o.w, c.w, lp);
        }
    }
    if (tid < 4) {
        int j = (tid < 3) ? tid : (NN - 1);
        float c = Cr[j];
        float cp = ui * __expf(-c * INV_EPS) * vs[j];
        Or[j] = cp;
        lp = fmaf(cp, c, lp);
    }

    #pragma unroll
    for (int o = 16; o > 0; o >>= 1) lp += __shfl_down_sync(0xffffffffu, lp, o);
    __shared__ float sh[8];
    if ((tid & 31) == 0) sh[tid >> 5] = lp;
    __syncthreads();
    if (tid == 0) {
        float t = 0.0f;
        #pragma unroll
        for (int w = 0; w < 8; w++) t += sh[w];
        g_losspart[i] = t;
    }
}

__global__ void loss_kernel(float* __restrict__ out) {
    __shared__ float sh[1024];
    float s = 0.0f;
    for (int i = threadIdx.x; i < NN; i += 1024) s += g_losspart[i];
    sh[threadIdx.x] = s;
    __syncthreads();
    for (int o = 512; o > 0; o >>= 1) {
        if (threadIdx.x < o) sh[threadIdx.x] += sh[threadIdx.x + o];
        __syncthreads();
    }
    if (threadIdx.x == 0) out[0] = sh[0] * (1.0f / ((float)NN * (float)NN));
}

extern "C" void kernel_launch(void* const* d_in, const int* in_sizes, int n_in,
                              void* d_out, int out_size) {
    const float* S = (const float*)d_in[0];
    const float* T = (const float*)d_in[1];
    float* out = (float*)d_out;
    // layout: [ loss(1) | coupling(NN*NN) | C(NN*NN) ]
    float* coupling = out + 1;
    float* Cmat     = out + 1 + (size_t)NN * NN;

    cudaFuncSetAttribute(gemm_kernel, cudaFuncAttributeMaxDynamicSharedMemorySize, SMEM_DYN);

    cvt_norm_kernel<<<dim3(NN, 2), 128>>>(S, T);
    init_v_kernel<<<16, 256>>>();
    gemm_kernel<<<dim3(32, 32), 512, SMEM_DYN>>>(Cmat);

    for (int it = 0; it < 10; it++) {
        row_mv_kernel<<<NN, 512>>>();
        col_mv_part_kernel<<<dim3(2, 128), 256>>>();
        col_reduce_kernel<<<16, 256>>>();
    }

    final_kernel<<<NN, 256>>>(coupling, Cmat);
    loss_kernel<<<1, 1024>>>(out);
}

// round 12
// speedup vs baseline: 1.3223x; 1.3223x over previous
#include <cuda_runtime.h>
#include <cuda_fp16.h>
#include <math.h>
#include <stdint.h>

#define NN 4096
#define DD 512
#define INV_EPS 0.125f
#define STABZ 1e-8f

// ---- device scratch (no allocations allowed) ----
__device__ __half g_Sh[(size_t)NN * DD];     // fp16 source features
__device__ __half g_Th[(size_t)NN * DD];     // fp16 target features
__device__ float  g_u[NN];
__device__ float  g_v[NN];
__device__ float  g_sn[NN];
__device__ float  g_tn[NN];
__device__ __half g_Kh[(size_t)NN * NN];     // 32 MB fp16 Gibbs kernel for Sinkhorn matvecs
__device__ float  g_colpart[128 * NN];
__device__ float  g_losspart[NN];

// ================= helpers =================
__device__ __forceinline__ uint32_t s2u(const void* p) {
    uint32_t a;
    asm("{ .reg .u64 t; cvta.to.shared.u64 t, %1; cvt.u32.u64 %0, t; }" : "=r"(a) : "l"(p));
    return a;
}
#define SW128(o) ((o) ^ (((o) >> 3) & 0x70))

__device__ __forceinline__ void cp16(uint32_t dst, const void* src) {
    asm volatile("cp.async.cg.shared.global [%0], [%1], 16;" :: "r"(dst), "l"(src));
}

__device__ __forceinline__ void ldm4(uint32_t& r0, uint32_t& r1, uint32_t& r2, uint32_t& r3,
                                     uint32_t addr) {
    asm volatile("ldmatrix.sync.aligned.m8n8.x4.shared.b16 {%0,%1,%2,%3}, [%4];"
                 : "=r"(r0), "=r"(r1), "=r"(r2), "=r"(r3) : "r"(addr));
}

__device__ __forceinline__ void mma16816h(float* c, const uint32_t* a, const uint32_t* b) {
    asm volatile(
        "mma.sync.aligned.m16n8k16.row.col.f32.f16.f16.f32 "
        "{%0,%1,%2,%3}, {%4,%5,%6,%7}, {%8,%9}, {%0,%1,%2,%3};"
        : "+f"(c[0]), "+f"(c[1]), "+f"(c[2]), "+f"(c[3])
        : "r"(a[0]), "r"(a[1]), "r"(a[2]), "r"(a[3]), "r"(b[0]), "r"(b[1]));
}

// ================= fused norm + fp16 convert =================
__global__ void cvt_norm_kernel(const float* __restrict__ S, const float* __restrict__ T) {
    const float* src = blockIdx.y ? T : S;
    __half*       hi = blockIdx.y ? g_Th : g_Sh;
    float*       dst = blockIdx.y ? g_tn : g_sn;
    const int row = blockIdx.x;
    const int base = row * DD + threadIdx.x * 4;
    float4 x = *(const float4*)(src + base);

    *(__half2*)(hi + base)     = __floats2half2_rn(x.x, x.y);
    *(__half2*)(hi + base + 2) = __floats2half2_rn(x.z, x.w);

    float s = x.x * x.x + x.y * x.y + x.z * x.z + x.w * x.w;
    #pragma unroll
    for (int o = 16; o > 0; o >>= 1) s += __shfl_down_sync(0xffffffffu, s, o);
    __shared__ float sh[4];
    if ((threadIdx.x & 31) == 0) sh[threadIdx.x >> 5] = s;
    __syncthreads();
    if (threadIdx.x == 0) dst[row] = sh[0] + sh[1] + sh[2] + sh[3];
}

__global__ void init_v_kernel() {
    int i = blockIdx.x * 256 + threadIdx.x;
    if (i < NN) g_v[i] = 1.0f;
}

// ================= fp16 mma.sync GEMM + fused epilogue =================
// D = S@T^T in fp16 (fp32 accum). C = sqrt(max(sn+tn-2D,0)); Kh = fp16(exp(-C/8)).
// 128x128 CTA tile, BK=64, 4-stage cp.async pipeline, one barrier per chunk.
#define TILE_B 16384                  // one 128x64 fp16 tile
#define STAGE_B (2 * TILE_B)          // A, B = 32 KB
#define SMEM_DYN (4 * STAGE_B)        // 131072 (4 stages)

__global__ __launch_bounds__(512, 1)
void gemm_kernel(float* __restrict__ Cout) {
    extern __shared__ char smem[];
    const uint32_t sb = s2u(smem);
    const int tid = threadIdx.x, wid = tid >> 5, lid = tid & 31;
    const int wr = wid & 3, wc = wid >> 2;       // warp tile: rows wr*32, cols wc*32
    const int row0 = blockIdx.y * 128;
    const int col0 = blockIdx.x * 128;

    const __half* gA = g_Sh + (size_t)row0 * DD;
    const __half* gB = g_Th + (size_t)col0 * DD;

    // per-thread load coords: each tile = 1024 chunks of 16B; 512 threads -> 2 per tile
    const int lrow0 = tid >> 3, lrow1 = (tid + 512) >> 3;
    const int lcb = tid & 7;

    // ldmatrix per-lane address components (validated mapping)
    const int mi = lid >> 3, r8 = lid & 7;
    const int a_row = wr * 32 + (mi & 1) * 8 + r8;        // + m*16
    const int a_cb  = (mi >> 1) * 16;                     // + ks*32
    const int b_row = wc * 32 + (mi & 2) * 4 + r8;        // + g*16
    const int b_cb  = (mi & 1) * 16;                      // + ks*32

    float acc[2][4][4];
    #pragma unroll
    for (int m = 0; m < 2; m++)
        #pragma unroll
        for (int n = 0; n < 4; n++)
            #pragma unroll
            for (int q = 0; q < 4; q++) acc[m][n][q] = 0.0f;

    // prologue: load chunks 0,1,2 into stages 0,1,2
    #pragma unroll
    for (int s = 0; s < 3; s++) {
        uint32_t tb = sb + s * STAGE_B;
        const __half* ga = gA + s * 64;
        const __half* gb = gB + s * 64;
        cp16(tb + SW128((uint32_t)(lrow0 * 128 + lcb * 16)),
             (const void*)(ga + (size_t)lrow0 * DD + lcb * 8));
        cp16(tb + SW128((uint32_t)(lrow1 * 128 + lcb * 16)),
             (const void*)(ga + (size_t)lrow1 * DD + lcb * 8));
        cp16(tb + TILE_B + SW128((uint32_t)(lrow0 * 128 + lcb * 16)),
             (const void*)(gb + (size_t)lrow0 * DD + lcb * 8));
        cp16(tb + TILE_B + SW128((uint32_t)(lrow1 * 128 + lcb * 16)),
             (const void*)(gb + (size_t)lrow1 * DD + lcb * 8));
        asm volatile("cp.async.commit_group;");
    }

    for (int ch = 0; ch < 8; ch++) {
        if (ch <= 5)      asm volatile("cp.async.wait_group 2;" ::: "memory");
        else if (ch == 6) asm volatile("cp.async.wait_group 1;" ::: "memory");
        else              asm volatile("cp.async.wait_group 0;" ::: "memory");
        // single barrier: stage ch ready AND stage (ch-1) consumed by all warps
        __syncthreads();

        if (ch < 5) {
            uint32_t tb = sb + ((ch + 3) & 3) * STAGE_B;
            const __half* ga = gA + (ch + 3) * 64;
            const __half* gb = gB + (ch + 3) * 64;
            cp16(tb + SW128((uint32_t)(lrow0 * 128 + lcb * 16)),
                 (const void*)(ga + (size_t)lrow0 * DD + lcb * 8));
            cp16(tb + SW128((uint32_t)(lrow1 * 128 + lcb * 16)),
                 (const void*)(ga + (size_t)lrow1 * DD + lcb * 8));
            cp16(tb + TILE_B + SW128((uint32_t)(lrow0 * 128 + lcb * 16)),
                 (const void*)(gb + (size_t)lrow0 * DD + lcb * 8));
            cp16(tb + TILE_B + SW128((uint32_t)(lrow1 * 128 + lcb * 16)),
                 (const void*)(gb + (size_t)lrow1 * DD + lcb * 8));
            asm volatile("cp.async.commit_group;");
        }

        const uint32_t cur = sb + (ch & 3) * STAGE_B;
        const uint32_t tA = cur, tB = cur + TILE_B;
        #pragma unroll
        for (int ks = 0; ks < 4; ks++) {
            const int cb = ks * 32;
            uint32_t ah[2][4], bh[4][2];
            #pragma unroll
            for (int m = 0; m < 2; m++) {
                uint32_t off = SW128((uint32_t)((a_row + m * 16) * 128 + a_cb + cb));
                ldm4(ah[m][0], ah[m][1], ah[m][2], ah[m][3], tA + off);
            }
            #pragma unroll
            for (int g = 0; g < 2; g++) {
                uint32_t off = SW128((uint32_t)((b_row + g * 16) * 128 + b_cb + cb));
                ldm4(bh[2 * g][0], bh[2 * g][1], bh[2 * g + 1][0], bh[2 * g + 1][1], tB + off);
            }
            #pragma unroll
            for (int m = 0; m < 2; m++)
                #pragma unroll
                for (int n = 0; n < 4; n++)
                    mma16816h(acc[m][n], ah[m], bh[n]);
        }
    }
    __syncthreads();   // before reusing smem for the epilogue stage

    // ---- epilogue: convert to C, stage in smem, coalesced global stores ----
    float* sm = (float*)smem;    // 128 x 129 fp32
    const int qr = lid >> 2, qc = lid & 3;
    #pragma unroll
    for (int m = 0; m < 2; m++) {
        const int rb = wr * 32 + m * 16 + qr;
        const float sn0 = g_sn[row0 + rb];
        const float sn1 = g_sn[row0 + rb + 8];
        #pragma unroll
        for (int n = 0; n < 4; n++) {
            const int cl = wc * 32 + n * 8 + 2 * qc;
            const float tn0 = __ldg(&g_tn[col0 + cl]);
            const float tn1 = __ldg(&g_tn[col0 + cl + 1]);
            sm[rb * 129 + cl]           = sqrtf(fmaxf(sn0 + tn0 - 2.0f * acc[m][n][0], 0.0f));
            sm[rb * 129 + cl + 1]       = sqrtf(fmaxf(sn0 + tn1 - 2.0f * acc[m][n][1], 0.0f));
            sm[(rb + 8) * 129 + cl]     = sqrtf(fmaxf(sn1 + tn0 - 2.0f * acc[m][n][2], 0.0f));
            sm[(rb + 8) * 129 + cl + 1] = sqrtf(fmaxf(sn1 + tn1 - 2.0f * acc[m][n][3], 0.0f));
        }
    }
    __syncthreads();

    #pragma unroll 4
    for (int it = 0; it < 32; it++) {
        int lin = it * 512 + tid;
        int r = lin >> 7, c = lin & 127;
        Cout[(size_t)(row0 + r) * NN + col0 + c] = sm[r * 129 + c];
    }
    __half2* Kh2 = (__half2*)g_Kh;
    #pragma unroll 4
    for (int it = 0; it < 16; it++) {
        int lin = it * 512 + tid;
        int r = lin >> 6, c2 = lin & 63;
        float a = sm[r * 129 + 2 * c2];
        float b = sm[r * 129 + 2 * c2 + 1];
        Kh2[((size_t)(row0 + r) * NN + col0) / 2 + c2] =
            __floats2half2_rn(__expf(-a * INV_EPS), __expf(-b * INV_EPS));
    }
}

// ================= Sinkhorn =================
// 8 rows per 256-thread block; v staged once in smem (cuts v traffic 8x).
__global__ __launch_bounds__(256)
void row_mv_kernel() {
    __shared__ float vs[NN];   // 16 KB
    const int tid = threadIdx.x;
    {
        const float4* V4 = (const float4*)g_v;
        float4* S4 = (float4*)vs;
        #pragma unroll
        for (int p = 0; p < 4; p++) S4[tid + p * 256] = V4[tid + p * 256];
    }
    __syncthreads();

    const int wid = tid >> 5, lid = tid & 31;
    const int row = blockIdx.x * 8 + wid;
    const uint4* Kr = (const uint4*)(g_Kh + (size_t)row * NN);   // 512 uint4 per row
    float sum = 0.0f;
    #pragma unroll 4
    for (int p = 0; p < 16; p++) {
        const int j2 = lid + p * 32;
        uint4 q = Kr[j2];
        const float4 v0 = *(const float4*)&vs[8 * j2];
        const float4 v1 = *(const float4*)&vs[8 * j2 + 4];
        float2 f0 = __half22float2(*(const __half2*)&q.x);
        float2 f1 = __half22float2(*(const __half2*)&q.y);
        float2 f2 = __half22float2(*(const __half2*)&q.z);
        float2 f3 = __half22float2(*(const __half2*)&q.w);
        sum = fmaf(f0.x, v0.x, sum); sum = fmaf(f0.y, v0.y, sum);
        sum = fmaf(f1.x, v0.z, sum); sum = fmaf(f1.y, v0.w, sum);
        sum = fmaf(f2.x, v1.x, sum); sum = fmaf(f2.y, v1.y, sum);
        sum = fmaf(f3.x, v1.z, sum); sum = fmaf(f3.y, v1.w, sum);
    }
    #pragma unroll
    for (int o = 16; o > 0; o >>= 1) sum += __shfl_down_sync(0xffffffffu, sum, o);
    if (lid == 0) g_u[row] = (1.0f / NN) / (sum + STABZ);
}

// partials over 32-row chunks: grid (2, 128) = 256 blocks
__global__ __launch_bounds__(256)
void col_mv_part_kernel() {
    const int cb = blockIdx.x * 256 + threadIdx.x;   // uint4 index within row (0..511)
    const int i0 = blockIdx.y * 32;
    __shared__ float ush[32];
    if (threadIdx.x < 32) ush[threadIdx.x] = g_u[i0 + threadIdx.x];
    __syncthreads();
    float a0 = 0, a1 = 0, a2 = 0, a3 = 0, a4 = 0, a5 = 0, a6 = 0, a7 = 0;
    #pragma unroll 8
    for (int ii = 0; ii < 32; ii++) {
        uint4 q = *(const uint4*)(g_Kh + (size_t)(i0 + ii) * NN + cb * 8);
        float u = ush[ii];
        float2 f0 = __half22float2(*(const __half2*)&q.x);
        float2 f1 = __half22float2(*(const __half2*)&q.y);
        float2 f2 = __half22float2(*(const __half2*)&q.z);
        float2 f3 = __half22float2(*(const __half2*)&q.w);
        a0 = fmaf(f0.x, u, a0); a1 = fmaf(f0.y, u, a1);
        a2 = fmaf(f1.x, u, a2); a3 = fmaf(f1.y, u, a3);
        a4 = fmaf(f2.x, u, a4); a5 = fmaf(f2.y, u, a5);
        a6 = fmaf(f3.x, u, a6); a7 = fmaf(f3.y, u, a7);
    }
    float4* P = (float4*)(g_colpart + blockIdx.y * NN + cb * 8);
    P[0] = make_float4(a0, a1, a2, a3);
    P[1] = make_float4(a4, a5, a6, a7);
}

__global__ void col_reduce_kernel() {
    int j = blockIdx.x * 256 + threadIdx.x;
    float s = 0.0f;
    #pragma unroll 8
    for (int ch = 0; ch < 128; ch++) s += g_colpart[ch * NN + j];
    g_v[j] = (1.0f / NN) / (s + STABZ);
}

// ================= final: coupling = u*exp(-C/8)*v, loss partials =================
// coup/Cc row bases are (1 mod 4) floats off 16B alignment: float4 body starts
// at element 3 (aligned); head elems 0..2 and tail elem 4095 handled scalar.
__global__ __launch_bounds__(256)
void final_kernel(float* __restrict__ coup, const float* __restrict__ Cc) {
    __shared__ float vs[NN];
    const int tid = threadIdx.x;
    {
        const float4* V4 = (const float4*)g_v;
        float4* S4 = (float4*)vs;
        #pragma unroll
        for (int p = 0; p < 4; p++) S4[tid + p * 256] = V4[tid + p * 256];
    }
    __syncthreads();

    const int i = blockIdx.x;
    const float ui = g_u[i];
    const float* Cr = Cc + (size_t)i * NN;
    float*       Or = coup + (size_t)i * NN;
    const float4* Cr4 = (const float4*)(Cr + 3);   // 16B aligned
    float4*       Or4 = (float4*)(Or + 3);
    float lp = 0.0f;

    #pragma unroll
    for (int p = 0; p < 4; p++) {
        int idx = tid + p * 256;
        if (idx < 1023) {
            float4 c = Cr4[idx];
            int j = 3 + 4 * idx;
            float4 o;
            o.x = ui * __expf(-c.x * INV_EPS) * vs[j];
            o.y = ui * __expf(-c.y * INV_EPS) * vs[j + 1];
            o.z = ui * __expf(-c.z * INV_EPS) * vs[j + 2];
            o.w = ui * __expf(-c.w * INV_EPS) * vs[j + 3];
            Or4[idx] = o;
            lp = fmaf(o.x, c.x, lp); lp = fmaf(o.y, c.y, lp);
            lp = fmaf(o.z, c.z, lp); lp = fmaf(o.w, c.w, lp);
        }
    }
    if (tid < 4) {
        int j = (tid < 3) ? tid : (NN - 1);
        float c = Cr[j];
        float cp = ui * __expf(-c * INV_EPS) * vs[j];
        Or[j] = cp;
        lp = fmaf(cp, c, lp);
    }

    #pragma unroll
    for (int o = 16; o > 0; o >>= 1) lp += __shfl_down_sync(0xffffffffu, lp, o);
    __shared__ float sh[8];
    if ((tid & 31) == 0) sh[tid >> 5] = lp;
    __syncthreads();
    if (tid == 0) {
        float t = 0.0f;
        #pragma unroll
        for (int w = 0; w < 8; w++) t += sh[w];
        g_losspart[i] = t;
    }
}

__global__ void loss_kernel(float* __restrict__ out) {
    __shared__ float sh[1024];
    float s = 0.0f;
    for (int i = threadIdx.x; i < NN; i += 1024) s += g_losspart[i];
    sh[threadIdx.x] = s;
    __syncthreads();
    for (int o = 512; o > 0; o >>= 1) {
        if (threadIdx.x < o) sh[threadIdx.x] += sh[threadIdx.x + o];
        __syncthreads();
    }
    if (threadIdx.x == 0) out[0] = sh[0] * (1.0f / ((float)NN * (float)NN));
}

extern "C" void kernel_launch(void* const* d_in, const int* in_sizes, int n_in,
                              void* d_out, int out_size) {
    const float* S = (const float*)d_in[0];
    const float* T = (const float*)d_in[1];
    float* out = (float*)d_out;
    // layout: [ loss(1) | coupling(NN*NN) | C(NN*NN) ]
    float* coupling = out + 1;
    float* Cmat     = out + 1 + (size_t)NN * NN;

    cudaFuncSetAttribute(gemm_kernel, cudaFuncAttributeMaxDynamicSharedMemorySize, SMEM_DYN);

    cvt_norm_kernel<<<dim3(NN, 2), 128>>>(S, T);
    init_v_kernel<<<16, 256>>>();
    gemm_kernel<<<dim3(32, 32), 512, SMEM_DYN>>>(Cmat);

    for (int it = 0; it < 10; it++) {
        row_mv_kernel<<<512, 256>>>();
        col_mv_part_kernel<<<dim3(2, 128), 256>>>();
        col_reduce_kernel<<<16, 256>>>();
    }

    final_kernel<<<NN, 256>>>(coupling, Cmat);
    loss_kernel<<<1, 1024>>>(out);
}